// round 12
// baseline (speedup 1.0000x reference)
#include <cuda_runtime.h>
#include <cuda_bf16.h>
#include <cstdint>
#include <math.h>

#define BB 2
#define SS 2048
#define HH 16
#define DD 128
#define HD 2048
#define WIN 256
#define GG 64
#define NPACK 2304   // 2048 q cols + 128 k_mean + 128 v_mean

__device__ float g_wpack[(size_t)HD * NPACK];
__device__ float g_bpack[NPACK];
__device__ float g_qraw[(size_t)BB * SS * NPACK];
__device__ float g_q[(size_t)BB * HH * SS * DD];
__device__ float g_km[(size_t)BB * SS * DD];
__device__ float g_vm[(size_t)BB * SS * DD];
__device__ float g_attn[(size_t)BB * SS * HD];
__device__ float g_hid_t[(size_t)BB * SS * HD];
__device__ float g_wo_t[(size_t)HD * HD];

__device__ __forceinline__ unsigned cvt_tf32_bits(float v) {
    unsigned t; asm("cvt.rna.tf32.f32 %0, %1;" : "=r"(t) : "f"(v)); return t;
}
__device__ __forceinline__ float cvt_tf32(float v) {
    return __uint_as_float(cvt_tf32_bits(v));
}
__device__ __forceinline__ void mma_tf32(float* acc, const unsigned* a, const unsigned* b) {
    asm volatile(
        "mma.sync.aligned.m16n8k8.row.col.f32.tf32.tf32.f32 "
        "{%0,%1,%2,%3}, {%4,%5,%6,%7}, {%8,%9}, {%0,%1,%2,%3};"
        : "+f"(acc[0]), "+f"(acc[1]), "+f"(acc[2]), "+f"(acc[3])
        : "r"(a[0]), "r"(a[1]), "r"(a[2]), "r"(a[3]), "r"(b[0]), "r"(b[1]));
}

__global__ __launch_bounds__(512)
void cvt_tf32_vec(const float4* __restrict__ in, float4* __restrict__ out, int n4)
{
    int i = blockIdx.x * blockDim.x + threadIdx.x;
    if (i < n4) {
        float4 v = in[i];
        v.x = cvt_tf32(v.x); v.y = cvt_tf32(v.y);
        v.z = cvt_tf32(v.z); v.w = cvt_tf32(v.w);
        out[i] = v;
    }
}

__global__ __launch_bounds__(256)
void pack_w(const float* __restrict__ W, float* __restrict__ Wp)
{
    long idx = (long)blockIdx.x * 256 + threadIdx.x;
    if (idx >= (long)HD * NPACK) return;
    int c = (int)(idx / NPACK), n = (int)(idx % NPACK);
    const float* row = W + (size_t)c * 6144;
    float v;
    if (n < 2048) {
        v = row[(n >> 7) * 384 + (n & 127)];
    } else {
        int off = 128 + (n - 2048);
        float s = 0.f;
#pragma unroll
        for (int h = 0; h < 16; ++h) s += row[h * 384 + off];
        v = s * 0.0625f;
    }
    Wp[idx] = cvt_tf32(v);
}

__global__ __launch_bounds__(256)
void pack_b(const float* __restrict__ bq, float* __restrict__ bp)
{
    int n = blockIdx.x * 256 + threadIdx.x;
    if (n >= NPACK) return;
    float v;
    if (n < 2048) v = bq[(n >> 7) * 384 + (n & 127)];
    else {
        int off = 128 + (n - 2048);
        float s = 0.f;
#pragma unroll
        for (int h = 0; h < 16; ++h) s += bq[h * 384 + off];
        v = s * 0.0625f;
    }
    bp[n] = v;
}

// ---------------- TF32 GEMM: BK=32, 3-stage ring (proven) ----------------
#define ASTRIDE 36
#define BSTRIDE 132
#define A_STG (128 * ASTRIDE)
#define B_STG (32 * BSTRIDE)
#define STG_FLOATS (A_STG + B_STG)
#define NSTAGE 3
#define GEMM_SMEM_BYTES (NSTAGE * STG_FLOATS * 4)

__global__ __launch_bounds__(256, 2)
void tf32_gemm_bias(const float* __restrict__ A, const float* __restrict__ B,
                    const float* __restrict__ bias, float* __restrict__ C,
                    int M, int N, int K)
{
    extern __shared__ float smem_g[];
    const int tid = threadIdx.x, lane = tid & 31, warp = tid >> 5;
    const int wm = warp >> 2, wn = warp & 3;
    const int brow = blockIdx.y, bcol = blockIdx.x;
    const float* Ab = A + (size_t)brow * 128 * K;
    const float* Bb = B + (size_t)bcol * 128;
    const int nk = K >> 5;

    float acc[4][4][4];
#pragma unroll
    for (int i = 0; i < 4; i++)
#pragma unroll
        for (int j = 0; j < 4; j++)
#pragma unroll
            for (int r = 0; r < 4; r++) acc[i][j][r] = 0.f;

    auto issue = [&](int kt) {
        int k0 = kt << 5;
        float* st = smem_g + (kt % NSTAGE) * STG_FLOATS;
#pragma unroll
        for (int l = 0; l < 4; ++l) {
            int ca = l * 256 + tid;
            int m = ca >> 3, k4 = (ca & 7) << 2;
            unsigned da = (unsigned)__cvta_generic_to_shared(st + m * ASTRIDE + k4);
            asm volatile("cp.async.cg.shared.global [%0], [%1], 16;\n"
                         :: "r"(da), "l"(Ab + (size_t)m * K + k0 + k4));
            int kk = ca >> 5, n4 = (ca & 31) << 2;
            unsigned db = (unsigned)__cvta_generic_to_shared(st + A_STG + kk * BSTRIDE + n4);
            asm volatile("cp.async.cg.shared.global [%0], [%1], 16;\n"
                         :: "r"(db), "l"(Bb + (size_t)(k0 + kk) * N + n4));
        }
    };

    const int g = lane >> 2, c = lane & 3;
    const int a_base = (wm * 64 + g) * ASTRIDE + c;
    const int b_base = c * BSTRIDE + wn * 32 + g;

    auto compute = [&](int s) {
        const float* Ast = smem_g + s * STG_FLOATS;
        const float* Bst = Ast + A_STG;
#pragma unroll
        for (int ks = 0; ks < 4; ++ks) {
            int kb = ks * 8;
            unsigned af[4][4], bf[4][2];
#pragma unroll
            for (int mil = 0; mil < 4; ++mil) {
                const float* pa = Ast + a_base + mil * (16 * ASTRIDE) + kb;
                af[mil][0] = __float_as_uint(pa[0]);
                af[mil][1] = __float_as_uint(pa[8 * ASTRIDE]);
                af[mil][2] = __float_as_uint(pa[4]);
                af[mil][3] = __float_as_uint(pa[8 * ASTRIDE + 4]);
            }
#pragma unroll
            for (int nil = 0; nil < 4; ++nil) {
                const float* pb = Bst + b_base + kb * BSTRIDE + nil * 8;
                bf[nil][0] = __float_as_uint(pb[0]);
                bf[nil][1] = __float_as_uint(pb[4 * BSTRIDE]);
            }
#pragma unroll
            for (int mil = 0; mil < 4; ++mil)
#pragma unroll
                for (int nil = 0; nil < 4; ++nil)
                    mma_tf32(acc[mil][nil], af[mil], bf[nil]);
        }
    };

    issue(0); asm volatile("cp.async.commit_group;");
    issue(1); asm volatile("cp.async.commit_group;");
    for (int kt = 0; kt < nk; ++kt) {
        asm volatile("cp.async.wait_group 1;");
        __syncthreads();
        compute(kt % NSTAGE);
        if (kt + 2 < nk) issue(kt + 2);
        asm volatile("cp.async.commit_group;");
    }

    const int tig = lane & 3;
#pragma unroll
    for (int mil = 0; mil < 4; ++mil)
#pragma unroll
        for (int nil = 0; nil < 4; ++nil) {
            int row0 = brow * 128 + wm * 64 + mil * 16 + g;
            int col  = bcol * 128 + wn * 32 + nil * 8 + tig * 2;
            float b0 = bias[col], b1 = bias[col + 1];
            *(float2*)(C + (size_t)row0 * N + col) =
                make_float2(acc[mil][nil][0] + b0, acc[mil][nil][1] + b1);
            *(float2*)(C + (size_t)(row0 + 8) * N + col) =
                make_float2(acc[mil][nil][2] + b0, acc[mil][nil][3] + b1);
        }
}

// ---------------- RoPE + split ----------------
__global__ __launch_bounds__(128)
void rope_split_kernel(const float* __restrict__ qraw, float* __restrict__ qout,
                       float* __restrict__ km, float* __restrict__ vm)
{
    int bs = blockIdx.x;
    int b = bs >> 11, s = bs & 2047;
    int d = threadIdx.x;
    const float* bp = qraw + (size_t)bs * NPACK;

    float c = 1.f, sn = 0.f;
    float sgn = (d < 16) ? -1.f : 1.f;
    if (d < 32) {
        float invf = (float)exp2(-(double)(d & 15) / 16.0 * log2(10000.0));
        float ang = (float)s * invf;
        c = (float)cos((double)ang);
        sn = (float)sin((double)ang);
    }

    float kv = bp[2048 + d];
    float vv = bp[2176 + d];
    float kp = __shfl_xor_sync(0xffffffffu, kv, 16);
    if (d < 32) kv = kv * c + sgn * kp * sn;
    km[(size_t)bs * 128 + d] = kv;
    vm[(size_t)bs * 128 + d] = vv;

#pragma unroll
    for (int h = 0; h < 16; ++h) {
        float qv = bp[h * 128 + d];
        float qp = __shfl_xor_sync(0xffffffffu, qv, 16);
        float qr = (d < 32) ? (qv * c + sgn * qp * sn) : qv;
        qout[(((size_t)(b * 16 + h)) * SS + s) * 128 + d] = qr;
    }
}

// ---------------- MMA attention: 16 heads/block, 1-term PV ----------------
#define OFF_K    0                       // K [64][132] = 8448
#define OFF_VH   8448                    // V [64][136] = 8704
#define OFF_P    17152                   // per warp 1088 floats x 16 warps = 17408
#define OFF_KPOS 34560                   // int[384]
#define OFF_KADD 34944                   // float[384]
#define ATTN2_FLOATS 35328
#define ATTN2_BYTES (ATTN2_FLOATS * 4)   // 141312 B

__global__ __launch_bounds__(512, 1)
void attn_mma(const float* __restrict__ q, const float* __restrict__ km,
              const float* __restrict__ vm, const float* __restrict__ mask,
              const int* __restrict__ gidx, float* __restrict__ out)
{
    extern __shared__ float sm[];
    int* kpos = (int*)(sm + OFF_KPOS);
    float* kadd = sm + OFF_KADD;

    const int qp0 = blockIdx.x * 16, b = blockIdx.y;
    const int tid = threadIdx.x, warp = tid >> 5, lane = tid & 31;
    const int g = lane >> 2, c2 = lane & 3, tig = c2;
    const bool caseA = (qp0 >= WIN);
    const int NCH = caseA ? 6 : ((qp0 + 79) >> 6);
    const float scale = 0.08838834764831845f;

    for (int j = tid; j < 384; j += 512) {
        int pos = 1 << 27; float ka = 0.f;
        if (caseA) {
            if (j < 64) pos = gidx[b * GG + j];
            else { int p = qp0 - 255 + (j - 64);
                   if (p < SS) { pos = p; ka = mask[b * SS + p]; } }
        } else if (j < qp0 + 16) { pos = j; ka = mask[b * SS + j]; }
        kpos[j] = pos; kadd[j] = ka;
    }

    const int h = warp;
    unsigned qf[16][4];
    {
        const float* qb = q + (((size_t)(b * 16 + h)) * SS + qp0) * 128;
#pragma unroll
        for (int ks = 0; ks < 16; ++ks) {
            int d0 = ks * 8 + c2;
            qf[ks][0] = cvt_tf32_bits(qb[g * 128 + d0] * scale);
            qf[ks][1] = cvt_tf32_bits(qb[(g + 8) * 128 + d0] * scale);
            qf[ks][2] = cvt_tf32_bits(qb[g * 128 + d0 + 4] * scale);
            qf[ks][3] = cvt_tf32_bits(qb[(g + 8) * 128 + d0 + 4] * scale);
        }
    }
    __syncthreads();

    float m0 = -1e30f, m1 = -1e30f, l0 = 0.f, l1 = 0.f;
    float oacc[16][4];
#pragma unroll
    for (int dt = 0; dt < 16; ++dt)
#pragma unroll
        for (int e = 0; e < 4; ++e) oacc[dt][e] = 0.f;

    float* Pw = sm + OFF_P + warp * 1088;     // hi [16][68]

    for (int ch = 0; ch < NCH; ++ch) {
        const int cb = ch << 6;
        const bool isglob = caseA && (ch == 0);

        {
            int r = tid >> 3, c0 = (tid & 7) * 16;
            int pos = kpos[cb + r]; if (pos >= SS) pos = 0;
            const float* kvp = km + ((size_t)b * SS + pos) * 128 + c0;
            const float* vvp = vm + ((size_t)b * SS + pos) * 128 + c0;
            float* kd = sm + OFF_K + r * 132 + c0;
            float* vh = sm + OFF_VH + r * 136 + c0;
#pragma unroll
            for (int j = 0; j < 4; ++j) {
                float4 a = *(const float4*)(kvp + j * 4);
                a.x = cvt_tf32(a.x); a.y = cvt_tf32(a.y);
                a.z = cvt_tf32(a.z); a.w = cvt_tf32(a.w);
                *(float4*)(kd + j * 4) = a;
                float4 v = *(const float4*)(vvp + j * 4);
                v.x = cvt_tf32(v.x); v.y = cvt_tf32(v.y);
                v.z = cvt_tf32(v.z); v.w = cvt_tf32(v.w);
                *(float4*)(vh + j * 4) = v;
            }
        }
        __syncthreads();

        float S[8][4];
#pragma unroll
        for (int nt = 0; nt < 8; ++nt)
#pragma unroll
            for (int e = 0; e < 4; ++e) S[nt][e] = 0.f;
#pragma unroll
        for (int ks = 0; ks < 16; ++ks) {
#pragma unroll
            for (int nt = 0; nt < 8; ++nt) {
                const float* pk = sm + OFF_K + (nt * 8 + g) * 132 + ks * 8 + c2;
                unsigned bf[2] = {__float_as_uint(pk[0]), __float_as_uint(pk[4])};
                mma_tf32(S[nt], qf[ks], bf);
            }
        }

        float mc0 = -2e30f, mc1 = -2e30f;
#pragma unroll
        for (int nt = 0; nt < 8; ++nt) {
            int s0 = cb + nt * 8 + 2 * tig;
#pragma unroll
            for (int e = 0; e < 2; ++e) {
                int p = kpos[s0 + e]; float ka = kadd[s0 + e];
                int r0 = qp0 + g, r1 = r0 + 8;
                bool v0, v1;
                if (isglob) { v0 = p < r0 - 256; v1 = p < r1 - 256; }
                else { v0 = (p <= r0) && (p + 255 >= r0);
                       v1 = (p <= r1) && (p + 255 >= r1); }
                S[nt][e]     = v0 ? S[nt][e] + ka     : -2e30f;
                S[nt][e + 2] = v1 ? S[nt][e + 2] + ka : -2e30f;
                mc0 = fmaxf(mc0, S[nt][e]);
                mc1 = fmaxf(mc1, S[nt][e + 2]);
            }
        }
        mc0 = fmaxf(mc0, __shfl_xor_sync(~0u, mc0, 1));
        mc0 = fmaxf(mc0, __shfl_xor_sync(~0u, mc0, 2));
        mc1 = fmaxf(mc1, __shfl_xor_sync(~0u, mc1, 1));
        mc1 = fmaxf(mc1, __shfl_xor_sync(~0u, mc1, 2));
        float mn0 = fmaxf(m0, mc0), mn1 = fmaxf(m1, mc1);
        float cr0 = __expf(m0 - mn0), cr1 = __expf(m1 - mn1);
        m0 = mn0; m1 = mn1;
        float lc0 = 0.f, lc1 = 0.f;
#pragma unroll
        for (int nt = 0; nt < 8; ++nt) {
            S[nt][0] = __expf(S[nt][0] - mn0); S[nt][1] = __expf(S[nt][1] - mn0);
            S[nt][2] = __expf(S[nt][2] - mn1); S[nt][3] = __expf(S[nt][3] - mn1);
            lc0 += S[nt][0] + S[nt][1]; lc1 += S[nt][2] + S[nt][3];
        }
        lc0 += __shfl_xor_sync(~0u, lc0, 1); lc0 += __shfl_xor_sync(~0u, lc0, 2);
        lc1 += __shfl_xor_sync(~0u, lc1, 1); lc1 += __shfl_xor_sync(~0u, lc1, 2);
        l0 = l0 * cr0 + lc0; l1 = l1 * cr1 + lc1;
#pragma unroll
        for (int dt = 0; dt < 16; ++dt) {
            oacc[dt][0] *= cr0; oacc[dt][1] *= cr0;
            oacc[dt][2] *= cr1; oacc[dt][3] *= cr1;
        }
        // store P (tf32-rounded), fragment layout stride 68
#pragma unroll
        for (int nt = 0; nt < 8; ++nt) {
            int col = nt * 8 + 2 * tig;
            *(float2*)(Pw + g * 68 + col) =
                make_float2(cvt_tf32(S[nt][0]), cvt_tf32(S[nt][1]));
            *(float2*)(Pw + (g + 8) * 68 + col) =
                make_float2(cvt_tf32(S[nt][2]), cvt_tf32(S[nt][3]));
        }
        __syncwarp();

        // PV: single-term
#pragma unroll
        for (int pk = 0; pk < 8; ++pk) {
            const float* ph = Pw + pk * 8 + c2;
            unsigned ah[4] = {__float_as_uint(ph[g * 68]),
                              __float_as_uint(ph[(g + 8) * 68]),
                              __float_as_uint(ph[g * 68 + 4]),
                              __float_as_uint(ph[(g + 8) * 68 + 4])};
#pragma unroll
            for (int dt = 0; dt < 16; ++dt) {
                const float* vh = sm + OFF_VH + (pk * 8 + c2) * 136 + dt * 8 + g;
                unsigned bh[2] = {__float_as_uint(vh[0]), __float_as_uint(vh[4 * 136])};
                mma_tf32(oacc[dt], ah, bh);
            }
        }
        __syncthreads();
    }

    float inv0 = 1.f / l0, inv1 = 1.f / l1;
    float* o0 = out + ((size_t)b * SS + qp0 + g) * HD + h * 128 + 2 * tig;
    float* o1 = out + ((size_t)b * SS + qp0 + g + 8) * HD + h * 128 + 2 * tig;
#pragma unroll
    for (int dt = 0; dt < 16; ++dt) {
        *(float2*)(o0 + dt * 8) = make_float2(cvt_tf32(oacc[dt][0] * inv0),
                                              cvt_tf32(oacc[dt][1] * inv0));
        *(float2*)(o1 + dt * 8) = make_float2(cvt_tf32(oacc[dt][2] * inv1),
                                              cvt_tf32(oacc[dt][3] * inv1));
    }
}

// ---------------------------------------------------------------------------
extern "C" void kernel_launch(void* const* d_in, const int* in_sizes, int n_in,
                              void* d_out, int out_size)
{
    const float* hidden = (const float*)d_in[0];
    const float* mask   = (const float*)d_in[1];
    const int*   gidx   = (const int*)d_in[2];
    const float* Wqkv   = (const float*)d_in[3];
    const float* bqkv   = (const float*)d_in[4];
    const float* Wo     = (const float*)d_in[5];
    const float* bo     = (const float*)d_in[6];
    float* out = (float*)d_out;

    float *wpack, *bpack, *qraw, *qbuf, *kmp, *vmp, *attn, *hid_t, *wo_t;
    cudaGetSymbolAddress((void**)&wpack, g_wpack);
    cudaGetSymbolAddress((void**)&bpack, g_bpack);
    cudaGetSymbolAddress((void**)&qraw,  g_qraw);
    cudaGetSymbolAddress((void**)&qbuf,  g_q);
    cudaGetSymbolAddress((void**)&kmp,   g_km);
    cudaGetSymbolAddress((void**)&vmp,   g_vm);
    cudaGetSymbolAddress((void**)&attn,  g_attn);
    cudaGetSymbolAddress((void**)&hid_t, g_hid_t);
    cudaGetSymbolAddress((void**)&wo_t,  g_wo_t);

    cudaFuncSetAttribute(attn_mma, cudaFuncAttributeMaxDynamicSharedMemorySize,
                         ATTN2_BYTES);
    cudaFuncSetAttribute(tf32_gemm_bias, cudaFuncAttributeMaxDynamicSharedMemorySize,
                         GEMM_SMEM_BYTES);

    {
        long nw = (long)HD * NPACK;
        pack_w<<<(unsigned)((nw + 255) / 256), 256>>>(Wqkv, wpack);
        pack_b<<<(NPACK + 255) / 256, 256>>>(bqkv, bpack);
        int n4h = (BB * SS * HD) / 4, n4o = (HD * HD) / 4;
        cvt_tf32_vec<<<(n4h + 511) / 512, 512>>>((const float4*)hidden,
                                                 (float4*)hid_t, n4h);
        cvt_tf32_vec<<<(n4o + 511) / 512, 512>>>((const float4*)Wo,
                                                 (float4*)wo_t, n4o);
    }

    tf32_gemm_bias<<<dim3(NPACK / 128, 4096 / 128), 256, GEMM_SMEM_BYTES>>>(
        hid_t, wpack, bpack, qraw, 4096, NPACK, 2048);

    rope_split_kernel<<<BB * SS, 128>>>(qraw, qbuf, kmp, vmp);

    attn_mma<<<dim3(SS / 16, BB), 512, ATTN2_BYTES>>>(
        qbuf, kmp, vmp, mask, gidx, attn);

    tf32_gemm_bias<<<dim3(2048 / 128, 4096 / 128), 256, GEMM_SMEM_BYTES>>>(
        attn, wo_t, bo, out, 4096, 2048, 2048);
}

// round 13
// speedup vs baseline: 1.1501x; 1.1501x over previous
#include <cuda_runtime.h>
#include <cuda_bf16.h>
#include <cstdint>
#include <math.h>

#define BB 2
#define SS 2048
#define HH 16
#define DD 128
#define HD 2048
#define WIN 256
#define GG 64
#define NPACK 2304   // 2048 q cols + 128 k_mean + 128 v_mean

// fragment-order operands (see layout notes above)
__device__ float g_apermH[(size_t)4096 * 2048];      // hidden, A_perm
__device__ float g_attnP[(size_t)4096 * 2048];       // attn out, A_perm
__device__ float g_wpackP[(size_t)18 * 64 * 4096];   // packed Wqkv, B_perm
__device__ float g_woP[(size_t)16 * 64 * 4096];      // Wo, B_perm
__device__ float g_bpack[NPACK];
__device__ float g_qraw[(size_t)BB * SS * NPACK];
__device__ float g_q[(size_t)BB * HH * SS * DD];
__device__ float g_km[(size_t)BB * SS * DD];
__device__ float g_vm[(size_t)BB * SS * DD];

__device__ __forceinline__ unsigned cvt_tf32_bits(float v) {
    unsigned t; asm("cvt.rna.tf32.f32 %0, %1;" : "=r"(t) : "f"(v)); return t;
}
__device__ __forceinline__ float cvt_tf32(float v) {
    return __uint_as_float(cvt_tf32_bits(v));
}
__device__ __forceinline__ void mma_tf32(float* acc, const unsigned* a, const unsigned* b) {
    asm volatile(
        "mma.sync.aligned.m16n8k8.row.col.f32.tf32.tf32.f32 "
        "{%0,%1,%2,%3}, {%4,%5,%6,%7}, {%8,%9}, {%0,%1,%2,%3};"
        : "+f"(acc[0]), "+f"(acc[1]), "+f"(acc[2]), "+f"(acc[3])
        : "r"(a[0]), "r"(a[1]), "r"(a[2]), "r"(a[3]), "r"(b[0]), "r"(b[1]));
}

// ---------------- A_perm builder: X[4096][2048] -> fragment order ----------------
// [brow][kt][ks][mt][lane][r]; m = brow*128+mt*16+(lane>>2)+(r&1)*8,
// k = kt*32+ks*8+(lane&3)+(r>>1)*4
__global__ __launch_bounds__(256)
void a_perm(const float* __restrict__ X, float* __restrict__ out)
{
    long i = (long)blockIdx.x * 256 + threadIdx.x;
    if (i >= (long)4096 * 2048) return;
    int r = i & 3, lane = (i >> 2) & 31, mt = (i >> 7) & 7;
    int ks = (i >> 10) & 3, kt = (i >> 12) & 63, brow = (int)(i >> 18);
    int m = brow * 128 + mt * 16 + (lane >> 2) + (r & 1) * 8;
    int k = kt * 32 + ks * 8 + (lane & 3) + (r >> 1) * 4;
    out[i] = cvt_tf32(X[(size_t)m * 2048 + k]);
}

// ---------------- B_perm builder for weights ----------------
// [bcol][kt][ks][nt][lane][j]; n = bcol*128+nt*8+(lane>>2),
// k = kt*32+ks*8+(lane&3)+j*4.  mode 0: Wo [2048][2048] direct.
// mode 1: Wqkv [2048][6144] with q-gather / head-mean packing.
__global__ __launch_bounds__(256)
void pack_w_perm(const float* __restrict__ W, float* __restrict__ out,
                 int nbcol, int mode)
{
    long i = (long)blockIdx.x * 256 + threadIdx.x;
    if (i >= (long)nbcol * 262144) return;
    int j = i & 1, lane = (i >> 1) & 31, nt = (i >> 6) & 15;
    int ks = (i >> 10) & 3, kt = (i >> 12) & 63, bcol = (int)(i >> 18);
    int np = bcol * 128 + nt * 8 + (lane >> 2);
    int kk = kt * 32 + ks * 8 + (lane & 3) + j * 4;
    float v;
    if (mode == 0) {
        v = W[(size_t)kk * 2048 + np];
    } else if (np < 2048) {
        v = W[(size_t)kk * 6144 + (np >> 7) * 384 + (np & 127)];
    } else {
        int off = 128 + (np - 2048);
        float s = 0.f;
#pragma unroll
        for (int h = 0; h < 16; ++h) s += W[(size_t)kk * 6144 + h * 384 + off];
        v = s * 0.0625f;
    }
    out[i] = cvt_tf32(v);
}

__global__ __launch_bounds__(256)
void pack_b(const float* __restrict__ bq, float* __restrict__ bp)
{
    int n = blockIdx.x * 256 + threadIdx.x;
    if (n >= NPACK) return;
    float v;
    if (n < 2048) v = bq[(n >> 7) * 384 + (n & 127)];
    else {
        int off = 128 + (n - 2048);
        float s = 0.f;
#pragma unroll
        for (int h = 0; h < 16; ++h) s += bq[h * 384 + off];
        v = s * 0.0625f;
    }
    bp[n] = v;
}

// ---------------- TF32 GEMM on fragment-order operands ----------------
// C[M,N] = A@B + bias; A_perm/B_perm as above; BK=32, 3-stage cp.async ring.
#define STG_FLOATS 8192                  // A 4096 + B 4096 per stage
#define NSTAGE 3
#define GEMM_SMEM_BYTES (NSTAGE * STG_FLOATS * 4)   // 98304

__global__ __launch_bounds__(256, 2)
void tf32_gemm_perm(const float* __restrict__ Ap, const float* __restrict__ Bp,
                    const float* __restrict__ bias, float* __restrict__ C,
                    int M, int N, int K)
{
    extern __shared__ float smem_g[];
    const int tid = threadIdx.x, lane = tid & 31, warp = tid >> 5;
    const int wm = warp >> 2, wn = warp & 3;
    const int brow = blockIdx.y, bcol = blockIdx.x;
    const int nk = K >> 5;
    const float* Abase = Ap + (size_t)brow * nk * 4096;
    const float* Bbase = Bp + (size_t)bcol * nk * 4096;

    float acc[4][4][4];
#pragma unroll
    for (int i = 0; i < 4; i++)
#pragma unroll
        for (int j = 0; j < 4; j++)
#pragma unroll
            for (int r = 0; r < 4; r++) acc[i][j][r] = 0.f;

    auto issue = [&](int kt) {
        float* st = smem_g + (kt % NSTAGE) * STG_FLOATS;
        const float* sa = Abase + (size_t)kt * 4096;
        const float* sb = Bbase + (size_t)kt * 4096;
#pragma unroll
        for (int l = 0; l < 4; ++l) {
            int ca = l * 256 + tid;                 // 0..1023 chunks of 16B
            unsigned da = (unsigned)__cvta_generic_to_shared(st + ca * 4);
            asm volatile("cp.async.cg.shared.global [%0], [%1], 16;\n"
                         :: "r"(da), "l"(sa + ca * 4));
            unsigned db = (unsigned)__cvta_generic_to_shared(st + 4096 + ca * 4);
            asm volatile("cp.async.cg.shared.global [%0], [%1], 16;\n"
                         :: "r"(db), "l"(sb + ca * 4));
        }
    };

    auto compute = [&](int s) {
        const float* Ast = smem_g + s * STG_FLOATS;
        const float* Bst = Ast + 4096;
#pragma unroll
        for (int ks = 0; ks < 4; ++ks) {
            unsigned af[4][4], bf[4][2];
#pragma unroll
            for (int mil = 0; mil < 4; ++mil) {
                float4 v = *(const float4*)(Ast + ((ks * 8 + wm * 4 + mil) * 32 + lane) * 4);
                af[mil][0] = __float_as_uint(v.x);
                af[mil][1] = __float_as_uint(v.y);
                af[mil][2] = __float_as_uint(v.z);
                af[mil][3] = __float_as_uint(v.w);
            }
#pragma unroll
            for (int nil = 0; nil < 4; ++nil) {
                float2 v = *(const float2*)(Bst + ((ks * 16 + wn * 4 + nil) * 32 + lane) * 2);
                bf[nil][0] = __float_as_uint(v.x);
                bf[nil][1] = __float_as_uint(v.y);
            }
#pragma unroll
            for (int mil = 0; mil < 4; ++mil)
#pragma unroll
                for (int nil = 0; nil < 4; ++nil)
                    mma_tf32(acc[mil][nil], af[mil], bf[nil]);
        }
    };

    issue(0); asm volatile("cp.async.commit_group;");
    issue(1); asm volatile("cp.async.commit_group;");
    for (int kt = 0; kt < nk; ++kt) {
        asm volatile("cp.async.wait_group 1;");
        __syncthreads();
        compute(kt % NSTAGE);
        if (kt + 2 < nk) issue(kt + 2);
        asm volatile("cp.async.commit_group;");
    }

    const int g = lane >> 2, tig = lane & 3;
#pragma unroll
    for (int mil = 0; mil < 4; ++mil)
#pragma unroll
        for (int nil = 0; nil < 4; ++nil) {
            int row0 = brow * 128 + wm * 64 + mil * 16 + g;
            int col  = bcol * 128 + wn * 32 + nil * 8 + tig * 2;
            float b0 = bias[col], b1 = bias[col + 1];
            *(float2*)(C + (size_t)row0 * N + col) =
                make_float2(acc[mil][nil][0] + b0, acc[mil][nil][1] + b1);
            *(float2*)(C + (size_t)(row0 + 8) * N + col) =
                make_float2(acc[mil][nil][2] + b0, acc[mil][nil][3] + b1);
        }
}

// ---------------- RoPE + split (unchanged) ----------------
__global__ __launch_bounds__(128)
void rope_split_kernel(const float* __restrict__ qraw, float* __restrict__ qout,
                       float* __restrict__ km, float* __restrict__ vm)
{
    int bs = blockIdx.x;
    int b = bs >> 11, s = bs & 2047;
    int d = threadIdx.x;
    const float* bp = qraw + (size_t)bs * NPACK;

    float c = 1.f, sn = 0.f;
    float sgn = (d < 16) ? -1.f : 1.f;
    if (d < 32) {
        float invf = (float)exp2(-(double)(d & 15) / 16.0 * log2(10000.0));
        float ang = (float)s * invf;
        c = (float)cos((double)ang);
        sn = (float)sin((double)ang);
    }

    float kv = bp[2048 + d];
    float vv = bp[2176 + d];
    float kp = __shfl_xor_sync(0xffffffffu, kv, 16);
    if (d < 32) kv = kv * c + sgn * kp * sn;
    km[(size_t)bs * 128 + d] = kv;
    vm[(size_t)bs * 128 + d] = vv;

#pragma unroll
    for (int h = 0; h < 16; ++h) {
        float qv = bp[h * 128 + d];
        float qp = __shfl_xor_sync(0xffffffffu, qv, 16);
        float qr = (d < 32) ? (qv * c + sgn * qp * sn) : qv;
        qout[(((size_t)(b * 16 + h)) * SS + s) * 128 + d] = qr;
    }
}

// ---------------- MMA attention (round-12 proven; epilogue -> A_perm) ----------------
#define OFF_K    0
#define OFF_VH   8448
#define OFF_P    17152
#define OFF_KPOS 34560
#define OFF_KADD 34944
#define ATTN2_FLOATS 35328
#define ATTN2_BYTES (ATTN2_FLOATS * 4)

__global__ __launch_bounds__(512, 1)
void attn_mma(const float* __restrict__ q, const float* __restrict__ km,
              const float* __restrict__ vm, const float* __restrict__ mask,
              const int* __restrict__ gidx, float* __restrict__ attnP)
{
    extern __shared__ float sm[];
    int* kpos = (int*)(sm + OFF_KPOS);
    float* kadd = sm + OFF_KADD;

    const int qp0 = blockIdx.x * 16, b = blockIdx.y;
    const int tid = threadIdx.x, warp = tid >> 5, lane = tid & 31;
    const int g = lane >> 2, c2 = lane & 3, tig = c2;
    const bool caseA = (qp0 >= WIN);
    const int NCH = caseA ? 6 : ((qp0 + 79) >> 6);
    const float scale = 0.08838834764831845f;

    for (int j = tid; j < 384; j += 512) {
        int pos = 1 << 27; float ka = 0.f;
        if (caseA) {
            if (j < 64) pos = gidx[b * GG + j];
            else { int p = qp0 - 255 + (j - 64);
                   if (p < SS) { pos = p; ka = mask[b * SS + p]; } }
        } else if (j < qp0 + 16) { pos = j; ka = mask[b * SS + j]; }
        kpos[j] = pos; kadd[j] = ka;
    }

    const int h = warp;
    unsigned qf[16][4];
    {
        const float* qb = q + (((size_t)(b * 16 + h)) * SS + qp0) * 128;
#pragma unroll
        for (int ks = 0; ks < 16; ++ks) {
            int d0 = ks * 8 + c2;
            qf[ks][0] = cvt_tf32_bits(qb[g * 128 + d0] * scale);
            qf[ks][1] = cvt_tf32_bits(qb[(g + 8) * 128 + d0] * scale);
            qf[ks][2] = cvt_tf32_bits(qb[g * 128 + d0 + 4] * scale);
            qf[ks][3] = cvt_tf32_bits(qb[(g + 8) * 128 + d0 + 4] * scale);
        }
    }
    __syncthreads();

    float m0 = -1e30f, m1 = -1e30f, l0 = 0.f, l1 = 0.f;
    float oacc[16][4];
#pragma unroll
    for (int dt = 0; dt < 16; ++dt)
#pragma unroll
        for (int e = 0; e < 4; ++e) oacc[dt][e] = 0.f;

    float* Pw = sm + OFF_P + warp * 1088;

    for (int ch = 0; ch < NCH; ++ch) {
        const int cb = ch << 6;
        const bool isglob = caseA && (ch == 0);

        {
            int r = tid >> 3, c0 = (tid & 7) * 16;
            int pos = kpos[cb + r]; if (pos >= SS) pos = 0;
            const float* kvp = km + ((size_t)b * SS + pos) * 128 + c0;
            const float* vvp = vm + ((size_t)b * SS + pos) * 128 + c0;
            float* kd = sm + OFF_K + r * 132 + c0;
            float* vh = sm + OFF_VH + r * 136 + c0;
#pragma unroll
            for (int j = 0; j < 4; ++j) {
                float4 a = *(const float4*)(kvp + j * 4);
                a.x = cvt_tf32(a.x); a.y = cvt_tf32(a.y);
                a.z = cvt_tf32(a.z); a.w = cvt_tf32(a.w);
                *(float4*)(kd + j * 4) = a;
                float4 v = *(const float4*)(vvp + j * 4);
                v.x = cvt_tf32(v.x); v.y = cvt_tf32(v.y);
                v.z = cvt_tf32(v.z); v.w = cvt_tf32(v.w);
                *(float4*)(vh + j * 4) = v;
            }
        }
        __syncthreads();

        float S[8][4];
#pragma unroll
        for (int nt = 0; nt < 8; ++nt)
#pragma unroll
            for (int e = 0; e < 4; ++e) S[nt][e] = 0.f;
#pragma unroll
        for (int ks = 0; ks < 16; ++ks) {
#pragma unroll
            for (int nt = 0; nt < 8; ++nt) {
                const float* pk = sm + OFF_K + (nt * 8 + g) * 132 + ks * 8 + c2;
                unsigned bf[2] = {__float_as_uint(pk[0]), __float_as_uint(pk[4])};
                mma_tf32(S[nt], qf[ks], bf);
            }
        }

        float mc0 = -2e30f, mc1 = -2e30f;
#pragma unroll
        for (int nt = 0; nt < 8; ++nt) {
            int s0 = cb + nt * 8 + 2 * tig;
#pragma unroll
            for (int e = 0; e < 2; ++e) {
                int p = kpos[s0 + e]; float ka = kadd[s0 + e];
                int r0 = qp0 + g, r1 = r0 + 8;
                bool v0, v1;
                if (isglob) { v0 = p < r0 - 256; v1 = p < r1 - 256; }
                else { v0 = (p <= r0) && (p + 255 >= r0);
                       v1 = (p <= r1) && (p + 255 >= r1); }
                S[nt][e]     = v0 ? S[nt][e] + ka     : -2e30f;
                S[nt][e + 2] = v1 ? S[nt][e + 2] + ka : -2e30f;
                mc0 = fmaxf(mc0, S[nt][e]);
                mc1 = fmaxf(mc1, S[nt][e + 2]);
            }
        }
        mc0 = fmaxf(mc0, __shfl_xor_sync(~0u, mc0, 1));
        mc0 = fmaxf(mc0, __shfl_xor_sync(~0u, mc0, 2));
        mc1 = fmaxf(mc1, __shfl_xor_sync(~0u, mc1, 1));
        mc1 = fmaxf(mc1, __shfl_xor_sync(~0u, mc1, 2));
        float mn0 = fmaxf(m0, mc0), mn1 = fmaxf(m1, mc1);
        float cr0 = __expf(m0 - mn0), cr1 = __expf(m1 - mn1);
        m0 = mn0; m1 = mn1;
        float lc0 = 0.f, lc1 = 0.f;
#pragma unroll
        for (int nt = 0; nt < 8; ++nt) {
            S[nt][0] = __expf(S[nt][0] - mn0); S[nt][1] = __expf(S[nt][1] - mn0);
            S[nt][2] = __expf(S[nt][2] - mn1); S[nt][3] = __expf(S[nt][3] - mn1);
            lc0 += S[nt][0] + S[nt][1]; lc1 += S[nt][2] + S[nt][3];
        }
        lc0 += __shfl_xor_sync(~0u, lc0, 1); lc0 += __shfl_xor_sync(~0u, lc0, 2);
        lc1 += __shfl_xor_sync(~0u, lc1, 1); lc1 += __shfl_xor_sync(~0u, lc1, 2);
        l0 = l0 * cr0 + lc0; l1 = l1 * cr1 + lc1;
#pragma unroll
        for (int dt = 0; dt < 16; ++dt) {
            oacc[dt][0] *= cr0; oacc[dt][1] *= cr0;
            oacc[dt][2] *= cr1; oacc[dt][3] *= cr1;
        }
#pragma unroll
        for (int nt = 0; nt < 8; ++nt) {
            int col = nt * 8 + 2 * tig;
            *(float2*)(Pw + g * 68 + col) =
                make_float2(cvt_tf32(S[nt][0]), cvt_tf32(S[nt][1]));
            *(float2*)(Pw + (g + 8) * 68 + col) =
                make_float2(cvt_tf32(S[nt][2]), cvt_tf32(S[nt][3]));
        }
        __syncwarp();

#pragma unroll
        for (int pk = 0; pk < 8; ++pk) {
            const float* ph = Pw + pk * 8 + c2;
            unsigned ah[4] = {__float_as_uint(ph[g * 68]),
                              __float_as_uint(ph[(g + 8) * 68]),
                              __float_as_uint(ph[g * 68 + 4]),
                              __float_as_uint(ph[(g + 8) * 68 + 4])};
#pragma unroll
            for (int dt = 0; dt < 16; ++dt) {
                const float* vh = sm + OFF_VH + (pk * 8 + c2) * 136 + dt * 8 + g;
                unsigned bh[2] = {__float_as_uint(vh[0]), __float_as_uint(vh[4 * 136])};
                mma_tf32(oacc[dt], ah, bh);
            }
        }
        __syncthreads();
    }

    // epilogue: write A_perm fragment-order global for GEMM2
    const float inv0 = 1.f / l0, inv1 = 1.f / l1;
    const int browA = (b * SS + qp0) >> 7;
    const int mt = (qp0 >> 4) & 7;
#pragma unroll
    for (int dt = 0; dt < 16; ++dt) {
#pragma unroll
        for (int e = 0; e < 4; ++e) {
            int k = h * 128 + dt * 8 + tig * 2 + (e & 1);
            int kt = k >> 5, ks = (k >> 3) & 3;
            int lanep = g * 4 + (k & 3);
            int r = ((e >> 1) & 1) + ((k >> 2) & 1) * 2;
            size_t off = ((size_t)(browA * 64 + kt)) * 4096
                       + (size_t)((ks * 8 + mt) * 128 + lanep * 4 + r);
            float sc = (e < 2) ? inv0 : inv1;
            attnP[off] = cvt_tf32(oacc[dt][e] * sc);
        }
    }
}

// ---------------------------------------------------------------------------
extern "C" void kernel_launch(void* const* d_in, const int* in_sizes, int n_in,
                              void* d_out, int out_size)
{
    const float* hidden = (const float*)d_in[0];
    const float* mask   = (const float*)d_in[1];
    const int*   gidx   = (const int*)d_in[2];
    const float* Wqkv   = (const float*)d_in[3];
    const float* bqkv   = (const float*)d_in[4];
    const float* Wo     = (const float*)d_in[5];
    const float* bo     = (const float*)d_in[6];
    float* out = (float*)d_out;

    float *apermH, *attnP, *wpackP, *woP, *bpack, *qraw, *qbuf, *kmp, *vmp;
    cudaGetSymbolAddress((void**)&apermH, g_apermH);
    cudaGetSymbolAddress((void**)&attnP,  g_attnP);
    cudaGetSymbolAddress((void**)&wpackP, g_wpackP);
    cudaGetSymbolAddress((void**)&woP,    g_woP);
    cudaGetSymbolAddress((void**)&bpack,  g_bpack);
    cudaGetSymbolAddress((void**)&qraw,   g_qraw);
    cudaGetSymbolAddress((void**)&qbuf,   g_q);
    cudaGetSymbolAddress((void**)&kmp,    g_km);
    cudaGetSymbolAddress((void**)&vmp,    g_vm);

    cudaFuncSetAttribute(attn_mma, cudaFuncAttributeMaxDynamicSharedMemorySize,
                         ATTN2_BYTES);
    cudaFuncSetAttribute(tf32_gemm_perm, cudaFuncAttributeMaxDynamicSharedMemorySize,
                         GEMM_SMEM_BYTES);

    // 0) operand prep (all fragment-order)
    pack_w_perm<<<(unsigned)(((long)18 * 262144 + 255) / 256), 256>>>(Wqkv, wpackP, 18, 1);
    pack_w_perm<<<(unsigned)(((long)16 * 262144 + 255) / 256), 256>>>(Wo, woP, 16, 0);
    pack_b<<<(NPACK + 255) / 256, 256>>>(bqkv, bpack);
    a_perm<<<(unsigned)(((long)4096 * 2048 + 255) / 256), 256>>>(hidden, apermH);

    // 1) fused Q + head-mean-KV GEMM: [4096,2048] @ [2048,2304] + b
    tf32_gemm_perm<<<dim3(NPACK / 128, 4096 / 128), 256, GEMM_SMEM_BYTES>>>(
        apermH, wpackP, bpack, qraw, 4096, NPACK, 2048);

    // 2) RoPE + split
    rope_split_kernel<<<BB * SS, 128>>>(qraw, qbuf, kmp, vmp);

    // 3) MMA attention (writes GEMM2's A operand in fragment order)
    attn_mma<<<dim3(SS / 16, BB), 512, ATTN2_BYTES>>>(
        qbuf, kmp, vmp, mask, gidx, attnP);

    // 4) Output GEMM: [4096,2048] @ [2048,2048] + b
    tf32_gemm_perm<<<dim3(2048 / 128, 4096 / 128), 256, GEMM_SMEM_BYTES>>>(
        attnP, woP, bo, out, 4096, 2048, 2048);
}

// round 14
// speedup vs baseline: 1.2222x; 1.0627x over previous
#include <cuda_runtime.h>
#include <cuda_bf16.h>
#include <cstdint>
#include <math.h>

#define BB 2
#define SS 2048
#define HH 16
#define DD 128
#define HD 2048
#define WIN 256
#define GG 64
#define NPACK 2304   // 2048 q cols + 128 k_mean + 128 v_mean

// fragment-order operands
__device__ float g_apermH[(size_t)4096 * 2048];      // hidden, A_perm
__device__ float g_attnP[(size_t)4096 * 2048];       // attn out, A_perm
__device__ float g_wpackP[(size_t)18 * 64 * 4096];   // packed Wqkv, B_perm
__device__ float g_woP[(size_t)16 * 64 * 4096];      // Wo, B_perm
__device__ float g_bpack[NPACK];
__device__ float g_qraw[(size_t)BB * SS * NPACK];
__device__ float g_qf[(size_t)BB * 128 * 16 * 2048]; // q, attn A-fragment order
__device__ float g_km[(size_t)BB * SS * DD];
__device__ float g_vm[(size_t)BB * SS * DD];

__device__ __forceinline__ unsigned cvt_tf32_bits(float v) {
    unsigned t; asm("cvt.rna.tf32.f32 %0, %1;" : "=r"(t) : "f"(v)); return t;
}
__device__ __forceinline__ float cvt_tf32(float v) {
    return __uint_as_float(cvt_tf32_bits(v));
}
__device__ __forceinline__ void mma_tf32(float* acc, const unsigned* a, const unsigned* b) {
    asm volatile(
        "mma.sync.aligned.m16n8k8.row.col.f32.tf32.tf32.f32 "
        "{%0,%1,%2,%3}, {%4,%5,%6,%7}, {%8,%9}, {%0,%1,%2,%3};"
        : "+f"(acc[0]), "+f"(acc[1]), "+f"(acc[2]), "+f"(acc[3])
        : "r"(a[0]), "r"(a[1]), "r"(a[2]), "r"(a[3]), "r"(b[0]), "r"(b[1]));
}

// ---------------- A_perm builder ----------------
__global__ __launch_bounds__(256)
void a_perm(const float* __restrict__ X, float* __restrict__ out)
{
    long i = (long)blockIdx.x * 256 + threadIdx.x;
    if (i >= (long)4096 * 2048) return;
    int r = i & 3, lane = (i >> 2) & 31, mt = (i >> 7) & 7;
    int ks = (i >> 10) & 3, kt = (i >> 12) & 63, brow = (int)(i >> 18);
    int m = brow * 128 + mt * 16 + (lane >> 2) + (r & 1) * 8;
    int k = kt * 32 + ks * 8 + (lane & 3) + (r >> 1) * 4;
    out[i] = cvt_tf32(X[(size_t)m * 2048 + k]);
}

// ---------------- B_perm builder ----------------
__global__ __launch_bounds__(256)
void pack_w_perm(const float* __restrict__ W, float* __restrict__ out,
                 int nbcol, int mode)
{
    long i = (long)blockIdx.x * 256 + threadIdx.x;
    if (i >= (long)nbcol * 262144) return;
    int j = i & 1, lane = (i >> 1) & 31, nt = (i >> 6) & 15;
    int ks = (i >> 10) & 3, kt = (i >> 12) & 63, bcol = (int)(i >> 18);
    int np = bcol * 128 + nt * 8 + (lane >> 2);
    int kk = kt * 32 + ks * 8 + (lane & 3) + j * 4;
    float v;
    if (mode == 0) {
        v = W[(size_t)kk * 2048 + np];
    } else if (np < 2048) {
        v = W[(size_t)kk * 6144 + (np >> 7) * 384 + (np & 127)];
    } else {
        int off = 128 + (np - 2048);
        float s = 0.f;
#pragma unroll
        for (int h = 0; h < 16; ++h) s += W[(size_t)kk * 6144 + h * 384 + off];
        v = s * 0.0625f;
    }
    out[i] = cvt_tf32(v);
}

__global__ __launch_bounds__(256)
void pack_b(const float* __restrict__ bq, float* __restrict__ bp)
{
    int n = blockIdx.x * 256 + threadIdx.x;
    if (n >= NPACK) return;
    float v;
    if (n < 2048) v = bq[(n >> 7) * 384 + (n & 127)];
    else {
        int off = 128 + (n - 2048);
        float s = 0.f;
#pragma unroll
        for (int h = 0; h < 16; ++h) s += bq[h * 384 + off];
        v = s * 0.0625f;
    }
    bp[n] = v;
}

// ---------------- TF32 GEMM on fragment-order operands (proven R13) ----------------
#define STG_FLOATS 8192
#define NSTAGE 3
#define GEMM_SMEM_BYTES (NSTAGE * STG_FLOATS * 4)

__global__ __launch_bounds__(256, 2)
void tf32_gemm_perm(const float* __restrict__ Ap, const float* __restrict__ Bp,
                    const float* __restrict__ bias, float* __restrict__ C,
                    int M, int N, int K)
{
    extern __shared__ float smem_g[];
    const int tid = threadIdx.x, lane = tid & 31, warp = tid >> 5;
    const int wm = warp >> 2, wn = warp & 3;
    const int brow = blockIdx.y, bcol = blockIdx.x;
    const int nk = K >> 5;
    const float* Abase = Ap + (size_t)brow * nk * 4096;
    const float* Bbase = Bp + (size_t)bcol * nk * 4096;

    float acc[4][4][4];
#pragma unroll
    for (int i = 0; i < 4; i++)
#pragma unroll
        for (int j = 0; j < 4; j++)
#pragma unroll
            for (int r = 0; r < 4; r++) acc[i][j][r] = 0.f;

    auto issue = [&](int kt) {
        float* st = smem_g + (kt % NSTAGE) * STG_FLOATS;
        const float* sa = Abase + (size_t)kt * 4096;
        const float* sb = Bbase + (size_t)kt * 4096;
#pragma unroll
        for (int l = 0; l < 4; ++l) {
            int ca = l * 256 + tid;
            unsigned da = (unsigned)__cvta_generic_to_shared(st + ca * 4);
            asm volatile("cp.async.cg.shared.global [%0], [%1], 16;\n"
                         :: "r"(da), "l"(sa + ca * 4));
            unsigned db = (unsigned)__cvta_generic_to_shared(st + 4096 + ca * 4);
            asm volatile("cp.async.cg.shared.global [%0], [%1], 16;\n"
                         :: "r"(db), "l"(sb + ca * 4));
        }
    };

    auto compute = [&](int s) {
        const float* Ast = smem_g + s * STG_FLOATS;
        const float* Bst = Ast + 4096;
#pragma unroll
        for (int ks = 0; ks < 4; ++ks) {
            unsigned af[4][4], bf[4][2];
#pragma unroll
            for (int mil = 0; mil < 4; ++mil) {
                float4 v = *(const float4*)(Ast + ((ks * 8 + wm * 4 + mil) * 32 + lane) * 4);
                af[mil][0] = __float_as_uint(v.x);
                af[mil][1] = __float_as_uint(v.y);
                af[mil][2] = __float_as_uint(v.z);
                af[mil][3] = __float_as_uint(v.w);
            }
#pragma unroll
            for (int nil = 0; nil < 4; ++nil) {
                float2 v = *(const float2*)(Bst + ((ks * 16 + wn * 4 + nil) * 32 + lane) * 2);
                bf[nil][0] = __float_as_uint(v.x);
                bf[nil][1] = __float_as_uint(v.y);
            }
#pragma unroll
            for (int mil = 0; mil < 4; ++mil)
#pragma unroll
                for (int nil = 0; nil < 4; ++nil)
                    mma_tf32(acc[mil][nil], af[mil], bf[nil]);
        }
    };

    issue(0); asm volatile("cp.async.commit_group;");
    issue(1); asm volatile("cp.async.commit_group;");
    for (int kt = 0; kt < nk; ++kt) {
        asm volatile("cp.async.wait_group 1;");
        __syncthreads();
        compute(kt % NSTAGE);
        if (kt + 2 < nk) issue(kt + 2);
        asm volatile("cp.async.commit_group;");
    }

    const int g = lane >> 2, tig = lane & 3;
#pragma unroll
    for (int mil = 0; mil < 4; ++mil)
#pragma unroll
        for (int nil = 0; nil < 4; ++nil) {
            int row0 = brow * 128 + wm * 64 + mil * 16 + g;
            int col  = bcol * 128 + wn * 32 + nil * 8 + tig * 2;
            float b0 = bias[col], b1 = bias[col + 1];
            *(float2*)(C + (size_t)row0 * N + col) =
                make_float2(acc[mil][nil][0] + b0, acc[mil][nil][1] + b1);
            *(float2*)(C + (size_t)(row0 + 8) * N + col) =
                make_float2(acc[mil][nil][2] + b0, acc[mil][nil][3] + b1);
        }
}

// ---------------- RoPE + split; q written PRE-SCALED, tf32, A-fragment order ----------------
__global__ __launch_bounds__(128)
void rope_split_kernel(const float* __restrict__ qraw, float* __restrict__ qf,
                       float* __restrict__ km, float* __restrict__ vm)
{
    int bs = blockIdx.x;
    int b = bs >> 11, s = bs & 2047;
    int d = threadIdx.x;
    const float* bp = qraw + (size_t)bs * NPACK;
    const float scale = 0.08838834764831845f;

    float c = 1.f, sn = 0.f;
    float sgn = (d < 16) ? -1.f : 1.f;
    if (d < 32) {
        float invf = (float)exp2(-(double)(d & 15) / 16.0 * log2(10000.0));
        float ang = (float)s * invf;
        c = (float)cos((double)ang);
        sn = (float)sin((double)ang);
    }

    float kv = bp[2048 + d];
    float vv = bp[2176 + d];
    float kp = __shfl_xor_sync(0xffffffffu, kv, 16);
    if (d < 32) kv = kv * c + sgn * kp * sn;
    km[(size_t)bs * 128 + d] = kv;
    vm[(size_t)bs * 128 + d] = vv;

    // fragment address for (qi, d)
    int qt = s >> 4, qi = s & 15;
    int lane = (qi & 7) * 4 + (d & 3);
    int r = (qi >> 3) + ((d >> 2) & 1) * 2;
    int ks = d >> 3;
    float* base = qf + ((size_t)(b * 128 + qt) * 16) * 2048 + ks * 128 + lane * 4 + r;
#pragma unroll
    for (int h = 0; h < 16; ++h) {
        float qv = bp[h * 128 + d];
        float qp = __shfl_xor_sync(0xffffffffu, qv, 16);
        float qr = (d < 32) ? (qv * c + sgn * qp * sn) : qv;
        base[(size_t)h * 2048] = cvt_tf32(qr * scale);
    }
}

// ---------------- MMA attention: Q fragments streamed from global (no spills) ----------------
#define OFF_K    0
#define OFF_VH   8448
#define OFF_P    17152
#define OFF_KPOS 34560
#define OFF_KADD 34944
#define ATTN2_FLOATS 35328
#define ATTN2_BYTES (ATTN2_FLOATS * 4)

__global__ __launch_bounds__(512, 1)
void attn_mma(const float* __restrict__ qf, const float* __restrict__ km,
              const float* __restrict__ vm, const float* __restrict__ mask,
              const int* __restrict__ gidx, float* __restrict__ attnP)
{
    extern __shared__ float sm[];
    int* kpos = (int*)(sm + OFF_KPOS);
    float* kadd = sm + OFF_KADD;

    const int qt = blockIdx.x, qp0 = qt * 16, b = blockIdx.y;
    const int tid = threadIdx.x, warp = tid >> 5, lane = tid & 31;
    const int g = lane >> 2, tig = lane & 3;
    const bool caseA = (qp0 >= WIN);
    const int NCH = caseA ? 6 : ((qp0 + 79) >> 6);

    for (int j = tid; j < 384; j += 512) {
        int pos = 1 << 27; float ka = 0.f;
        if (caseA) {
            if (j < 64) pos = gidx[b * GG + j];
            else { int p = qp0 - 255 + (j - 64);
                   if (p < SS) { pos = p; ka = mask[b * SS + p]; } }
        } else if (j < qp0 + 16) { pos = j; ka = mask[b * SS + j]; }
        kpos[j] = pos; kadd[j] = ka;
    }
    __syncthreads();

    const int h = warp;
    const float* qfb = qf + ((size_t)(b * 128 + qt) * 16 + h) * 2048;

    float m0 = -1e30f, m1 = -1e30f, l0 = 0.f, l1 = 0.f;
    float oacc[16][4];
#pragma unroll
    for (int dt = 0; dt < 16; ++dt)
#pragma unroll
        for (int e = 0; e < 4; ++e) oacc[dt][e] = 0.f;

    float* Pw = sm + OFF_P + warp * 1088;

    for (int ch = 0; ch < NCH; ++ch) {
        const int cb = ch << 6;
        const bool isglob = caseA && (ch == 0);

        {
            int r = tid >> 3, c0 = (tid & 7) * 16;
            int pos = kpos[cb + r]; if (pos >= SS) pos = 0;
            const float* kvp = km + ((size_t)b * SS + pos) * 128 + c0;
            const float* vvp = vm + ((size_t)b * SS + pos) * 128 + c0;
            float* kd = sm + OFF_K + r * 132 + c0;
            float* vh = sm + OFF_VH + r * 136 + c0;
#pragma unroll
            for (int j = 0; j < 4; ++j) {
                float4 a = *(const float4*)(kvp + j * 4);
                a.x = cvt_tf32(a.x); a.y = cvt_tf32(a.y);
                a.z = cvt_tf32(a.z); a.w = cvt_tf32(a.w);
                *(float4*)(kd + j * 4) = a;
                float4 v = *(const float4*)(vvp + j * 4);
                v.x = cvt_tf32(v.x); v.y = cvt_tf32(v.y);
                v.z = cvt_tf32(v.z); v.w = cvt_tf32(v.w);
                *(float4*)(vh + j * 4) = v;
            }
        }
        __syncthreads();

        float S[8][4];
#pragma unroll
        for (int nt = 0; nt < 8; ++nt)
#pragma unroll
            for (int e = 0; e < 4; ++e) S[nt][e] = 0.f;
#pragma unroll
        for (int ks = 0; ks < 16; ++ks) {
            float4 qv = *(const float4*)(qfb + ks * 128 + lane * 4);
            unsigned af[4] = {__float_as_uint(qv.x), __float_as_uint(qv.y),
                              __float_as_uint(qv.z), __float_as_uint(qv.w)};
#pragma unroll
            for (int nt = 0; nt < 8; ++nt) {
                const float* pk = sm + OFF_K + (nt * 8 + g) * 132 + ks * 8 + tig;
                unsigned bf[2] = {__float_as_uint(pk[0]), __float_as_uint(pk[4])};
                mma_tf32(S[nt], af, bf);
            }
        }

        float mc0 = -2e30f, mc1 = -2e30f;
#pragma unroll
        for (int nt = 0; nt < 8; ++nt) {
            int s0 = cb + nt * 8 + 2 * tig;
#pragma unroll
            for (int e = 0; e < 2; ++e) {
                int p = kpos[s0 + e]; float ka = kadd[s0 + e];
                int r0 = qp0 + g, r1 = r0 + 8;
                bool v0, v1;
                if (isglob) { v0 = p < r0 - 256; v1 = p < r1 - 256; }
                else { v0 = (p <= r0) && (p + 255 >= r0);
                       v1 = (p <= r1) && (p + 255 >= r1); }
                S[nt][e]     = v0 ? S[nt][e] + ka     : -2e30f;
                S[nt][e + 2] = v1 ? S[nt][e + 2] + ka : -2e30f;
                mc0 = fmaxf(mc0, S[nt][e]);
                mc1 = fmaxf(mc1, S[nt][e + 2]);
            }
        }
        mc0 = fmaxf(mc0, __shfl_xor_sync(~0u, mc0, 1));
        mc0 = fmaxf(mc0, __shfl_xor_sync(~0u, mc0, 2));
        mc1 = fmaxf(mc1, __shfl_xor_sync(~0u, mc1, 1));
        mc1 = fmaxf(mc1, __shfl_xor_sync(~0u, mc1, 2));
        float mn0 = fmaxf(m0, mc0), mn1 = fmaxf(m1, mc1);
        float cr0 = __expf(m0 - mn0), cr1 = __expf(m1 - mn1);
        m0 = mn0; m1 = mn1;
        float lc0 = 0.f, lc1 = 0.f;
#pragma unroll
        for (int nt = 0; nt < 8; ++nt) {
            S[nt][0] = __expf(S[nt][0] - mn0); S[nt][1] = __expf(S[nt][1] - mn0);
            S[nt][2] = __expf(S[nt][2] - mn1); S[nt][3] = __expf(S[nt][3] - mn1);
            lc0 += S[nt][0] + S[nt][1]; lc1 += S[nt][2] + S[nt][3];
        }
        lc0 += __shfl_xor_sync(~0u, lc0, 1); lc0 += __shfl_xor_sync(~0u, lc0, 2);
        lc1 += __shfl_xor_sync(~0u, lc1, 1); lc1 += __shfl_xor_sync(~0u, lc1, 2);
        l0 = l0 * cr0 + lc0; l1 = l1 * cr1 + lc1;
#pragma unroll
        for (int dt = 0; dt < 16; ++dt) {
            oacc[dt][0] *= cr0; oacc[dt][1] *= cr0;
            oacc[dt][2] *= cr1; oacc[dt][3] *= cr1;
        }
#pragma unroll
        for (int nt = 0; nt < 8; ++nt) {
            int col = nt * 8 + 2 * tig;
            *(float2*)(Pw + g * 68 + col) =
                make_float2(cvt_tf32(S[nt][0]), cvt_tf32(S[nt][1]));
            *(float2*)(Pw + (g + 8) * 68 + col) =
                make_float2(cvt_tf32(S[nt][2]), cvt_tf32(S[nt][3]));
        }
        __syncwarp();

#pragma unroll
        for (int pk = 0; pk < 8; ++pk) {
            const float* ph = Pw + pk * 8 + tig;
            unsigned ah[4] = {__float_as_uint(ph[g * 68]),
                              __float_as_uint(ph[(g + 8) * 68]),
                              __float_as_uint(ph[g * 68 + 4]),
                              __float_as_uint(ph[(g + 8) * 68 + 4])};
#pragma unroll
            for (int dt = 0; dt < 16; ++dt) {
                const float* vh = sm + OFF_VH + (pk * 8 + tig) * 136 + dt * 8 + g;
                unsigned bh[2] = {__float_as_uint(vh[0]), __float_as_uint(vh[4 * 136])};
                mma_tf32(oacc[dt], ah, bh);
            }
        }
        __syncthreads();
    }

    // epilogue: write A_perm fragment-order global for GEMM2 (proven R13)
    const float inv0 = 1.f / l0, inv1 = 1.f / l1;
    const int browA = (b * SS + qp0) >> 7;
    const int mt = (qp0 >> 4) & 7;
#pragma unroll
    for (int dt = 0; dt < 16; ++dt) {
#pragma unroll
        for (int e = 0; e < 4; ++e) {
            int k = h * 128 + dt * 8 + tig * 2 + (e & 1);
            int kt = k >> 5, ks = (k >> 3) & 3;
            int lanep = g * 4 + (k & 3);
            int r = ((e >> 1) & 1) + ((k >> 2) & 1) * 2;
            size_t off = ((size_t)(browA * 64 + kt)) * 4096
                       + (size_t)((ks * 8 + mt) * 128 + lanep * 4 + r);
            float sc = (e < 2) ? inv0 : inv1;
            attnP[off] = cvt_tf32(oacc[dt][e] * sc);
        }
    }
}

// ---------------------------------------------------------------------------
extern "C" void kernel_launch(void* const* d_in, const int* in_sizes, int n_in,
                              void* d_out, int out_size)
{
    const float* hidden = (const float*)d_in[0];
    const float* mask   = (const float*)d_in[1];
    const int*   gidx   = (const int*)d_in[2];
    const float* Wqkv   = (const float*)d_in[3];
    const float* bqkv   = (const float*)d_in[4];
    const float* Wo     = (const float*)d_in[5];
    const float* bo     = (const float*)d_in[6];
    float* out = (float*)d_out;

    float *apermH, *attnP, *wpackP, *woP, *bpack, *qraw, *qfb, *kmp, *vmp;
    cudaGetSymbolAddress((void**)&apermH, g_apermH);
    cudaGetSymbolAddress((void**)&attnP,  g_attnP);
    cudaGetSymbolAddress((void**)&wpackP, g_wpackP);
    cudaGetSymbolAddress((void**)&woP,    g_woP);
    cudaGetSymbolAddress((void**)&bpack,  g_bpack);
    cudaGetSymbolAddress((void**)&qraw,   g_qraw);
    cudaGetSymbolAddress((void**)&qfb,    g_qf);
    cudaGetSymbolAddress((void**)&kmp,    g_km);
    cudaGetSymbolAddress((void**)&vmp,    g_vm);

    cudaFuncSetAttribute(attn_mma, cudaFuncAttributeMaxDynamicSharedMemorySize,
                         ATTN2_BYTES);
    cudaFuncSetAttribute(tf32_gemm_perm, cudaFuncAttributeMaxDynamicSharedMemorySize,
                         GEMM_SMEM_BYTES);

    // 0) operand prep (all fragment-order)
    pack_w_perm<<<(unsigned)(((long)18 * 262144 + 255) / 256), 256>>>(Wqkv, wpackP, 18, 1);
    pack_w_perm<<<(unsigned)(((long)16 * 262144 + 255) / 256), 256>>>(Wo, woP, 16, 0);
    pack_b<<<(NPACK + 255) / 256, 256>>>(bqkv, bpack);
    a_perm<<<(unsigned)(((long)4096 * 2048 + 255) / 256), 256>>>(hidden, apermH);

    // 1) fused Q + head-mean-KV GEMM
    tf32_gemm_perm<<<dim3(NPACK / 128, 4096 / 128), 256, GEMM_SMEM_BYTES>>>(
        apermH, wpackP, bpack, qraw, 4096, NPACK, 2048);

    // 2) RoPE + split; q -> fragment order, pre-scaled tf32
    rope_split_kernel<<<BB * SS, 128>>>(qraw, qfb, kmp, vmp);

    // 3) MMA attention (Q streamed from global fragments; writes GEMM2 A_perm)
    attn_mma<<<dim3(SS / 16, BB), 512, ATTN2_BYTES>>>(
        qfb, kmp, vmp, mask, gidx, attnP);

    // 4) Output GEMM
    tf32_gemm_perm<<<dim3(2048 / 128, 4096 / 128), 256, GEMM_SMEM_BYTES>>>(
        attnP, woP, bo, out, 4096, 2048, 2048);
}

// round 15
// speedup vs baseline: 1.2394x; 1.0141x over previous
#include <cuda_runtime.h>
#include <cuda_bf16.h>
#include <cstdint>
#include <math.h>

#define BB 2
#define SS 2048
#define HH 16
#define DD 128
#define HD 2048
#define WIN 256
#define GG 64
#define NPACK 2304   // 2048 q cols + 128 k_mean + 128 v_mean

// fragment-order operands
__device__ float g_apermH[(size_t)4096 * 2048];      // hidden, A_perm
__device__ float g_attnP[(size_t)4096 * 2048];       // attn out, A_perm
__device__ float g_wpackP[(size_t)18 * 64 * 4096];   // packed Wqkv, B_perm
__device__ float g_woP[(size_t)16 * 64 * 4096];      // Wo, B_perm
__device__ float g_bpack[NPACK];
__device__ float g_qraw[(size_t)BB * SS * NPACK];
__device__ float g_qf[(size_t)BB * 128 * 16 * 2048]; // q, attn A-fragment order
__device__ float g_km[(size_t)BB * SS * DD];         // tf32-rounded
__device__ float g_vm[(size_t)BB * SS * DD];         // tf32-rounded

__device__ __forceinline__ unsigned cvt_tf32_bits(float v) {
    unsigned t; asm("cvt.rna.tf32.f32 %0, %1;" : "=r"(t) : "f"(v)); return t;
}
__device__ __forceinline__ float cvt_tf32(float v) {
    return __uint_as_float(cvt_tf32_bits(v));
}
__device__ __forceinline__ void mma_tf32(float* acc, const unsigned* a, const unsigned* b) {
    asm volatile(
        "mma.sync.aligned.m16n8k8.row.col.f32.tf32.tf32.f32 "
        "{%0,%1,%2,%3}, {%4,%5,%6,%7}, {%8,%9}, {%0,%1,%2,%3};"
        : "+f"(acc[0]), "+f"(acc[1]), "+f"(acc[2]), "+f"(acc[3])
        : "r"(a[0]), "r"(a[1]), "r"(a[2]), "r"(a[3]), "r"(b[0]), "r"(b[1]));
}

// ---------------- A_perm builder ----------------
__global__ __launch_bounds__(256)
void a_perm(const float* __restrict__ X, float* __restrict__ out)
{
    long i = (long)blockIdx.x * 256 + threadIdx.x;
    if (i >= (long)4096 * 2048) return;
    int r = i & 3, lane = (i >> 2) & 31, mt = (i >> 7) & 7;
    int ks = (i >> 10) & 3, kt = (i >> 12) & 63, brow = (int)(i >> 18);
    int m = brow * 128 + mt * 16 + (lane >> 2) + (r & 1) * 8;
    int k = kt * 32 + ks * 8 + (lane & 3) + (r >> 1) * 4;
    out[i] = cvt_tf32(X[(size_t)m * 2048 + k]);
}

// ---------------- B_perm builder ----------------
__global__ __launch_bounds__(256)
void pack_w_perm(const float* __restrict__ W, float* __restrict__ out,
                 int nbcol, int mode)
{
    long i = (long)blockIdx.x * 256 + threadIdx.x;
    if (i >= (long)nbcol * 262144) return;
    int j = i & 1, lane = (i >> 1) & 31, nt = (i >> 6) & 15;
    int ks = (i >> 10) & 3, kt = (i >> 12) & 63, bcol = (int)(i >> 18);
    int np = bcol * 128 + nt * 8 + (lane >> 2);
    int kk = kt * 32 + ks * 8 + (lane & 3) + j * 4;
    float v;
    if (mode == 0) {
        v = W[(size_t)kk * 2048 + np];
    } else if (np < 2048) {
        v = W[(size_t)kk * 6144 + (np >> 7) * 384 + (np & 127)];
    } else {
        int off = 128 + (np - 2048);
        float s = 0.f;
#pragma unroll
        for (int h = 0; h < 16; ++h) s += W[(size_t)kk * 6144 + h * 384 + off];
        v = s * 0.0625f;
    }
    out[i] = cvt_tf32(v);
}

__global__ __launch_bounds__(256)
void pack_b(const float* __restrict__ bq, float* __restrict__ bp)
{
    int n = blockIdx.x * 256 + threadIdx.x;
    if (n >= NPACK) return;
    float v;
    if (n < 2048) v = bq[(n >> 7) * 384 + (n & 127)];
    else {
        int off = 128 + (n - 2048);
        float s = 0.f;
#pragma unroll
        for (int h = 0; h < 16; ++h) s += bq[h * 384 + off];
        v = s * 0.0625f;
    }
    bp[n] = v;
}

// ---------------- TF32 GEMM on fragment-order operands (proven R13) ----------------
#define STG_FLOATS 8192
#define NSTAGE 3
#define GEMM_SMEM_BYTES (NSTAGE * STG_FLOATS * 4)

__global__ __launch_bounds__(256, 2)
void tf32_gemm_perm(const float* __restrict__ Ap, const float* __restrict__ Bp,
                    const float* __restrict__ bias, float* __restrict__ C,
                    int M, int N, int K)
{
    extern __shared__ float smem_g[];
    const int tid = threadIdx.x, lane = tid & 31, warp = tid >> 5;
    const int wm = warp >> 2, wn = warp & 3;
    const int brow = blockIdx.y, bcol = blockIdx.x;
    const int nk = K >> 5;
    const float* Abase = Ap + (size_t)brow * nk * 4096;
    const float* Bbase = Bp + (size_t)bcol * nk * 4096;

    float acc[4][4][4];
#pragma unroll
    for (int i = 0; i < 4; i++)
#pragma unroll
        for (int j = 0; j < 4; j++)
#pragma unroll
            for (int r = 0; r < 4; r++) acc[i][j][r] = 0.f;

    auto issue = [&](int kt) {
        float* st = smem_g + (kt % NSTAGE) * STG_FLOATS;
        const float* sa = Abase + (size_t)kt * 4096;
        const float* sb = Bbase + (size_t)kt * 4096;
#pragma unroll
        for (int l = 0; l < 4; ++l) {
            int ca = l * 256 + tid;
            unsigned da = (unsigned)__cvta_generic_to_shared(st + ca * 4);
            asm volatile("cp.async.cg.shared.global [%0], [%1], 16;\n"
                         :: "r"(da), "l"(sa + ca * 4));
            unsigned db = (unsigned)__cvta_generic_to_shared(st + 4096 + ca * 4);
            asm volatile("cp.async.cg.shared.global [%0], [%1], 16;\n"
                         :: "r"(db), "l"(sb + ca * 4));
        }
    };

    auto compute = [&](int s) {
        const float* Ast = smem_g + s * STG_FLOATS;
        const float* Bst = Ast + 4096;
#pragma unroll
        for (int ks = 0; ks < 4; ++ks) {
            unsigned af[4][4], bf[4][2];
#pragma unroll
            for (int mil = 0; mil < 4; ++mil) {
                float4 v = *(const float4*)(Ast + ((ks * 8 + wm * 4 + mil) * 32 + lane) * 4);
                af[mil][0] = __float_as_uint(v.x);
                af[mil][1] = __float_as_uint(v.y);
                af[mil][2] = __float_as_uint(v.z);
                af[mil][3] = __float_as_uint(v.w);
            }
#pragma unroll
            for (int nil = 0; nil < 4; ++nil) {
                float2 v = *(const float2*)(Bst + ((ks * 16 + wn * 4 + nil) * 32 + lane) * 2);
                bf[nil][0] = __float_as_uint(v.x);
                bf[nil][1] = __float_as_uint(v.y);
            }
#pragma unroll
            for (int mil = 0; mil < 4; ++mil)
#pragma unroll
                for (int nil = 0; nil < 4; ++nil)
                    mma_tf32(acc[mil][nil], af[mil], bf[nil]);
        }
    };

    issue(0); asm volatile("cp.async.commit_group;");
    issue(1); asm volatile("cp.async.commit_group;");
    for (int kt = 0; kt < nk; ++kt) {
        asm volatile("cp.async.wait_group 1;");
        __syncthreads();
        compute(kt % NSTAGE);
        if (kt + 2 < nk) issue(kt + 2);
        asm volatile("cp.async.commit_group;");
    }

    const int g = lane >> 2, tig = lane & 3;
#pragma unroll
    for (int mil = 0; mil < 4; ++mil)
#pragma unroll
        for (int nil = 0; nil < 4; ++nil) {
            int row0 = brow * 128 + wm * 64 + mil * 16 + g;
            int col  = bcol * 128 + wn * 32 + nil * 8 + tig * 2;
            float b0 = bias[col], b1 = bias[col + 1];
            *(float2*)(C + (size_t)row0 * N + col) =
                make_float2(acc[mil][nil][0] + b0, acc[mil][nil][1] + b1);
            *(float2*)(C + (size_t)(row0 + 8) * N + col) =
                make_float2(acc[mil][nil][2] + b0, acc[mil][nil][3] + b1);
        }
}

// ---------------- RoPE + split; q fragment-order; km/vm tf32-rounded ----------------
__global__ __launch_bounds__(128)
void rope_split_kernel(const float* __restrict__ qraw, float* __restrict__ qf,
                       float* __restrict__ km, float* __restrict__ vm)
{
    int bs = blockIdx.x;
    int b = bs >> 11, s = bs & 2047;
    int d = threadIdx.x;
    const float* bp = qraw + (size_t)bs * NPACK;
    const float scale = 0.08838834764831845f;

    float c = 1.f, sn = 0.f;
    float sgn = (d < 16) ? -1.f : 1.f;
    if (d < 32) {
        float invf = (float)exp2(-(double)(d & 15) / 16.0 * log2(10000.0));
        float ang = (float)s * invf;
        c = (float)cos((double)ang);
        sn = (float)sin((double)ang);
    }

    float kv = bp[2048 + d];
    float vv = bp[2176 + d];
    float kp = __shfl_xor_sync(0xffffffffu, kv, 16);
    if (d < 32) kv = kv * c + sgn * kp * sn;
    km[(size_t)bs * 128 + d] = cvt_tf32(kv);
    vm[(size_t)bs * 128 + d] = cvt_tf32(vv);

    int qt = s >> 4, qi = s & 15;
    int lane = (qi & 7) * 4 + (d & 3);
    int r = (qi >> 3) + ((d >> 2) & 1) * 2;
    int ks = d >> 3;
    float* base = qf + ((size_t)(b * 128 + qt) * 16) * 2048 + ks * 128 + lane * 4 + r;
#pragma unroll
    for (int h = 0; h < 16; ++h) {
        float qv = bp[h * 128 + d];
        float qp = __shfl_xor_sync(0xffffffffu, qv, 16);
        float qr = (d < 32) ? (qv * c + sgn * qp * sn) : qv;
        base[(size_t)h * 2048] = cvt_tf32(qr * scale);
    }
}

// ---------------- MMA attention: double-buffered cp.async K/V chunks ----------------
#define KSTG 8448                         // [64][132]
#define VSTG 8704                         // [64][136]
#define OFF_K0   0                        // 2 stages: 0, 8448
#define OFF_V0   16896                    // 2 stages: 16896, 25600
#define OFF_P    34304                    // per warp 1088 x 16 = 17408
#define OFF_KPOS 51712                    // int[384]
#define OFF_KADD 52096                    // float[384]
#define ATTN2_FLOATS 52480
#define ATTN2_BYTES (ATTN2_FLOATS * 4)    // 209920 B

__global__ __launch_bounds__(512, 1)
void attn_mma(const float* __restrict__ qf, const float* __restrict__ km,
              const float* __restrict__ vm, const float* __restrict__ mask,
              const int* __restrict__ gidx, float* __restrict__ attnP)
{
    extern __shared__ float sm[];
    int* kpos = (int*)(sm + OFF_KPOS);
    float* kadd = sm + OFF_KADD;

    const int qt = blockIdx.x, qp0 = qt * 16, b = blockIdx.y;
    const int tid = threadIdx.x, warp = tid >> 5, lane = tid & 31;
    const int g = lane >> 2, tig = lane & 3;
    const bool caseA = (qp0 >= WIN);
    const int NCH = caseA ? 6 : ((qp0 + 79) >> 6);

    for (int j = tid; j < 384; j += 512) {
        int pos = 1 << 27; float ka = 0.f;
        if (caseA) {
            if (j < 64) pos = gidx[b * GG + j];
            else { int p = qp0 - 255 + (j - 64);
                   if (p < SS) { pos = p; ka = mask[b * SS + p]; } }
        } else if (j < qp0 + 16) { pos = j; ka = mask[b * SS + j]; }
        kpos[j] = pos; kadd[j] = ka;
    }
    __syncthreads();

    // cp.async one K/V chunk into stage ch&1 (8 threads/row, 16 floats each)
    auto issue = [&](int ch) {
        int cb = ch << 6;
        int r = tid >> 3, q8 = (tid & 7) * 16;
        int pos = kpos[cb + r]; if (pos >= SS) pos = 0;
        const float* kvp = km + ((size_t)b * SS + pos) * 128 + q8;
        const float* vvp = vm + ((size_t)b * SS + pos) * 128 + q8;
        unsigned kd = (unsigned)__cvta_generic_to_shared(
            sm + OFF_K0 + (ch & 1) * KSTG + r * 132 + q8);
        unsigned vd = (unsigned)__cvta_generic_to_shared(
            sm + OFF_V0 + (ch & 1) * VSTG + r * 136 + q8);
#pragma unroll
        for (int j = 0; j < 4; ++j) {
            asm volatile("cp.async.cg.shared.global [%0], [%1], 16;\n"
                         :: "r"(kd + j * 16), "l"(kvp + j * 4));
            asm volatile("cp.async.cg.shared.global [%0], [%1], 16;\n"
                         :: "r"(vd + j * 16), "l"(vvp + j * 4));
        }
    };

    const int h = warp;
    const float* qfb = qf + ((size_t)(b * 128 + qt) * 16 + h) * 2048;

    float m0 = -1e30f, m1 = -1e30f, l0 = 0.f, l1 = 0.f;
    float oacc[16][4];
#pragma unroll
    for (int dt = 0; dt < 16; ++dt)
#pragma unroll
        for (int e = 0; e < 4; ++e) oacc[dt][e] = 0.f;

    float* Pw = sm + OFF_P + warp * 1088;

    issue(0);
    asm volatile("cp.async.commit_group;");

    for (int ch = 0; ch < NCH; ++ch) {
        if (ch + 1 < NCH) issue(ch + 1);
        asm volatile("cp.async.commit_group;");
        asm volatile("cp.async.wait_group 1;");
        __syncthreads();

        const int cb = ch << 6;
        const bool isglob = caseA && (ch == 0);
        const float* Kst = sm + OFF_K0 + (ch & 1) * KSTG;
        const float* Vst = sm + OFF_V0 + (ch & 1) * VSTG;

        float S[8][4];
#pragma unroll
        for (int nt = 0; nt < 8; ++nt)
#pragma unroll
            for (int e = 0; e < 4; ++e) S[nt][e] = 0.f;
#pragma unroll
        for (int ks = 0; ks < 16; ++ks) {
            float4 qv = *(const float4*)(qfb + ks * 128 + lane * 4);
            unsigned af[4] = {__float_as_uint(qv.x), __float_as_uint(qv.y),
                              __float_as_uint(qv.z), __float_as_uint(qv.w)};
#pragma unroll
            for (int nt = 0; nt < 8; ++nt) {
                const float* pk = Kst + (nt * 8 + g) * 132 + ks * 8 + tig;
                unsigned bf[2] = {__float_as_uint(pk[0]), __float_as_uint(pk[4])};
                mma_tf32(S[nt], af, bf);
            }
        }

        float mc0 = -2e30f, mc1 = -2e30f;
#pragma unroll
        for (int nt = 0; nt < 8; ++nt) {
            int s0 = cb + nt * 8 + 2 * tig;
#pragma unroll
            for (int e = 0; e < 2; ++e) {
                int p = kpos[s0 + e]; float ka = kadd[s0 + e];
                int r0 = qp0 + g, r1 = r0 + 8;
                bool v0, v1;
                if (isglob) { v0 = p < r0 - 256; v1 = p < r1 - 256; }
                else { v0 = (p <= r0) && (p + 255 >= r0);
                       v1 = (p <= r1) && (p + 255 >= r1); }
                S[nt][e]     = v0 ? S[nt][e] + ka     : -2e30f;
                S[nt][e + 2] = v1 ? S[nt][e + 2] + ka : -2e30f;
                mc0 = fmaxf(mc0, S[nt][e]);
                mc1 = fmaxf(mc1, S[nt][e + 2]);
            }
        }
        mc0 = fmaxf(mc0, __shfl_xor_sync(~0u, mc0, 1));
        mc0 = fmaxf(mc0, __shfl_xor_sync(~0u, mc0, 2));
        mc1 = fmaxf(mc1, __shfl_xor_sync(~0u, mc1, 1));
        mc1 = fmaxf(mc1, __shfl_xor_sync(~0u, mc1, 2));
        float mn0 = fmaxf(m0, mc0), mn1 = fmaxf(m1, mc1);
        float cr0 = __expf(m0 - mn0), cr1 = __expf(m1 - mn1);
        m0 = mn0; m1 = mn1;
        float lc0 = 0.f, lc1 = 0.f;
#pragma unroll
        for (int nt = 0; nt < 8; ++nt) {
            S[nt][0] = __expf(S[nt][0] - mn0); S[nt][1] = __expf(S[nt][1] - mn0);
            S[nt][2] = __expf(S[nt][2] - mn1); S[nt][3] = __expf(S[nt][3] - mn1);
            lc0 += S[nt][0] + S[nt][1]; lc1 += S[nt][2] + S[nt][3];
        }
        lc0 += __shfl_xor_sync(~0u, lc0, 1); lc0 += __shfl_xor_sync(~0u, lc0, 2);
        lc1 += __shfl_xor_sync(~0u, lc1, 1); lc1 += __shfl_xor_sync(~0u, lc1, 2);
        l0 = l0 * cr0 + lc0; l1 = l1 * cr1 + lc1;
#pragma unroll
        for (int dt = 0; dt < 16; ++dt) {
            oacc[dt][0] *= cr0; oacc[dt][1] *= cr0;
            oacc[dt][2] *= cr1; oacc[dt][3] *= cr1;
        }
#pragma unroll
        for (int nt = 0; nt < 8; ++nt) {
            int col = nt * 8 + 2 * tig;
            *(float2*)(Pw + g * 68 + col) =
                make_float2(cvt_tf32(S[nt][0]), cvt_tf32(S[nt][1]));
            *(float2*)(Pw + (g + 8) * 68 + col) =
                make_float2(cvt_tf32(S[nt][2]), cvt_tf32(S[nt][3]));
        }
        __syncwarp();

#pragma unroll
        for (int pk = 0; pk < 8; ++pk) {
            const float* ph = Pw + pk * 8 + tig;
            unsigned ah[4] = {__float_as_uint(ph[g * 68]),
                              __float_as_uint(ph[(g + 8) * 68]),
                              __float_as_uint(ph[g * 68 + 4]),
                              __float_as_uint(ph[(g + 8) * 68 + 4])};
#pragma unroll
            for (int dt = 0; dt < 16; ++dt) {
                const float* vh = Vst + (pk * 8 + tig) * 136 + dt * 8 + g;
                unsigned bh[2] = {__float_as_uint(vh[0]), __float_as_uint(vh[4 * 136])};
                mma_tf32(oacc[dt], ah, bh);
            }
        }
        __syncthreads();
    }

    // epilogue: write A_perm fragment-order global for GEMM2 (proven R13)
    const float inv0 = 1.f / l0, inv1 = 1.f / l1;
    const int browA = (b * SS + qp0) >> 7;
    const int mt = (qp0 >> 4) & 7;
#pragma unroll
    for (int dt = 0; dt < 16; ++dt) {
#pragma unroll
        for (int e = 0; e < 4; ++e) {
            int k = h * 128 + dt * 8 + tig * 2 + (e & 1);
            int kt = k >> 5, ks = (k >> 3) & 3;
            int lanep = g * 4 + (k & 3);
            int r = ((e >> 1) & 1) + ((k >> 2) & 1) * 2;
            size_t off = ((size_t)(browA * 64 + kt)) * 4096
                       + (size_t)((ks * 8 + mt) * 128 + lanep * 4 + r);
            float sc = (e < 2) ? inv0 : inv1;
            attnP[off] = cvt_tf32(oacc[dt][e] * sc);
        }
    }
}

// ---------------------------------------------------------------------------
extern "C" void kernel_launch(void* const* d_in, const int* in_sizes, int n_in,
                              void* d_out, int out_size)
{
    const float* hidden = (const float*)d_in[0];
    const float* mask   = (const float*)d_in[1];
    const int*   gidx   = (const int*)d_in[2];
    const float* Wqkv   = (const float*)d_in[3];
    const float* bqkv   = (const float*)d_in[4];
    const float* Wo     = (const float*)d_in[5];
    const float* bo     = (const float*)d_in[6];
    float* out = (float*)d_out;

    float *apermH, *attnP, *wpackP, *woP, *bpack, *qraw, *qfb, *kmp, *vmp;
    cudaGetSymbolAddress((void**)&apermH, g_apermH);
    cudaGetSymbolAddress((void**)&attnP,  g_attnP);
    cudaGetSymbolAddress((void**)&wpackP, g_wpackP);
    cudaGetSymbolAddress((void**)&woP,    g_woP);
    cudaGetSymbolAddress((void**)&bpack,  g_bpack);
    cudaGetSymbolAddress((void**)&qraw,   g_qraw);
    cudaGetSymbolAddress((void**)&qfb,    g_qf);
    cudaGetSymbolAddress((void**)&kmp,    g_km);
    cudaGetSymbolAddress((void**)&vmp,    g_vm);

    cudaFuncSetAttribute(attn_mma, cudaFuncAttributeMaxDynamicSharedMemorySize,
                         ATTN2_BYTES);
    cudaFuncSetAttribute(tf32_gemm_perm, cudaFuncAttributeMaxDynamicSharedMemorySize,
                         GEMM_SMEM_BYTES);

    // 0) operand prep (all fragment-order)
    pack_w_perm<<<(unsigned)(((long)18 * 262144 + 255) / 256), 256>>>(Wqkv, wpackP, 18, 1);
    pack_w_perm<<<(unsigned)(((long)16 * 262144 + 255) / 256), 256>>>(Wo, woP, 16, 0);
    pack_b<<<(NPACK + 255) / 256, 256>>>(bqkv, bpack);
    a_perm<<<(unsigned)(((long)4096 * 2048 + 255) / 256), 256>>>(hidden, apermH);

    // 1) fused Q + head-mean-KV GEMM
    tf32_gemm_perm<<<dim3(NPACK / 128, 4096 / 128), 256, GEMM_SMEM_BYTES>>>(
        apermH, wpackP, bpack, qraw, 4096, NPACK, 2048);

    // 2) RoPE + split; q -> fragment order, km/vm tf32-rounded
    rope_split_kernel<<<BB * SS, 128>>>(qraw, qfb, kmp, vmp);

    // 3) MMA attention (async double-buffered K/V; writes GEMM2 A_perm)
    attn_mma<<<dim3(SS / 16, BB), 512, ATTN2_BYTES>>>(
        qfb, kmp, vmp, mask, gidx, attnP);

    // 4) Output GEMM
    tf32_gemm_perm<<<dim3(2048 / 128, 4096 / 128), 256, GEMM_SMEM_BYTES>>>(
        attnP, woP, bo, out, 4096, 2048, 2048);
}